// round 16
// baseline (speedup 1.0000x reference)
#include <cuda_runtime.h>
#include <cuda_fp16.h>
#include <cstdint>

#define BATCH 8
#define IN_F 4096
#define OUT_F 12288
#define GS 128
#define NG 32
#define OPW 4          // outputs per warp
#define TPB 32         // one warp per CTA; NO intra-CTA sync anywhere
#define WDEPTH 4       // weight prefetch distance (groups)

typedef unsigned long long u64;

__device__ float  g_sx[BATCH * NG];      // per-batch per-group sums of x (fp32, exact)
__device__ __half g_xh[BATCH * IN_F];    // x as fp16 (64 KB, L1-resident)

__device__ __forceinline__ u64 pack2(float lo, float hi) {
    u64 r; asm("mov.b64 %0, {%1, %2};" : "=l"(r) : "f"(lo), "f"(hi)); return r;
}
__device__ __forceinline__ void unpack2(u64 v, float& lo, float& hi) {
    asm("mov.b64 {%0, %1}, %2;" : "=f"(lo), "=f"(hi) : "l"(v));
}
__device__ __forceinline__ u64 fma2(u64 a, u64 b, u64 c) {
    u64 d; asm("fma.rn.f32x2 %0, %1, %2, %3;" : "=l"(d) : "l"(a), "l"(b), "l"(c)); return d;
}
__device__ __forceinline__ u64 mul2(u64 a, u64 b) {
    u64 d; asm("mul.rn.f32x2 %0, %1, %2;" : "=l"(d) : "l"(a), "l"(b)); return d;
}
// weights: streaming, evict-first (protect x in L1)
__device__ __forceinline__ int4 ldg_cs(const int* p) {
    int4 v;
    asm("ld.global.cs.v4.u32 {%0,%1,%2,%3}, [%4];"
        : "=r"(v.x), "=r"(v.y), "=r"(v.z), "=r"(v.w) : "l"(p));
    return v;
}
// x (fp16): 8B per lane, keep resident in L1
__device__ __forceinline__ uint2 ldg_xh(const __half* p) {
    uint2 v;
    asm("ld.global.nc.L1::evict_last.v2.u32 {%0,%1}, [%2];"
        : "=r"(v.x), "=r"(v.y) : "l"(p));
    return v;
}
// scales: streaming
__device__ __forceinline__ float4 ldg_cs4(const float* p) {
    float4 v;
    asm("ld.global.cs.v4.f32 {%0,%1,%2,%3}, [%4];"
        : "=f"(v.x), "=f"(v.y), "=f"(v.z), "=f"(v.w) : "l"(p));
    return v;
}

// ---- prekernel: x -> fp16, plus Sx[b][g] group sums (warp per (b,g)) ----
__global__ void prep_kernel(const float* __restrict__ x) {
    const int gt   = blockIdx.x * blockDim.x + threadIdx.x;
    const int w    = gt >> 5;            // 0..255 = b*32 + g
    const int lane = gt & 31;
    const int base = (w >> 5) * IN_F + (w & 31) * GS + lane * 4;

    float4 v = __ldg((const float4*)(x + base));

    __half2 h01 = __floats2half2_rn(v.x, v.y);
    __half2 h23 = __floats2half2_rn(v.z, v.w);
    uint2 p;
    p.x = *(const unsigned*)&h01;
    p.y = *(const unsigned*)&h23;
    *(uint2*)(g_xh + base) = p;

    float s = (v.x + v.y) + (v.z + v.w);
    #pragma unroll
    for (int off = 16; off > 0; off >>= 1)
        s += __shfl_xor_sync(0xffffffffu, s, off);
    if (lane == 0) g_sx[w] = s;
}

// ---- main kernel: one warp per 4 outputs; front-batched; weight depth 4 ----
__global__ void __launch_bounds__(TPB, 10)
w4a32_main(const int* __restrict__ qw,
           const float* __restrict__ sc, const float* __restrict__ zr,
           float* __restrict__ out)
{
    __shared__ float bounce[OPW * BATCH];

    const int lane = threadIdx.x;
    const int n0   = blockIdx.x * OPW;
    const int klo  = lane * 4;

    const int* qbase = qw + (long)n0 * IN_F + klo;

    // weights: register pipeline depth 4
    int4 qbuf[WDEPTH][OPW];
    #pragma unroll
    for (int s = 0; s < WDEPTH; ++s)
        #pragma unroll
        for (int o = 0; o < OPW; ++o)
            qbuf[s][o] = ldg_cs(qbase + s * GS + o * IN_F);

    // scales: single buffer, distance 1 (captured before overwrite)
    float4 sv0 = ldg_cs4(sc + n0);

    // x (fp16 pairs): double buffer, distance 1
    uint2 xb[2][BATCH];
    #pragma unroll
    for (int b = 0; b < BATCH; ++b)
        xb[0][b] = ldg_xh(g_xh + b * IN_F + klo);

    u64 acc[OPW][BATCH];
    #pragma unroll
    for (int o = 0; o < OPW; ++o)
        #pragma unroll
        for (int b = 0; b < BATCH; ++b) acc[o][b] = 0ull;

    #pragma unroll 4
    for (int g = 0; g < NG; ++g) {
        const int cur  = g & 1;          // x parity
        const int wcur = g & (WDEPTH - 1);   // weight slot (static under unroll 4)

        // capture current group's operands before refill
        int4 q[OPW];
        #pragma unroll
        for (int o = 0; o < OPW; ++o) q[o] = qbuf[wcur][o];
        const float4 sv = sv0;

        // ========== FRONT-BATCHED LOAD BLOCK (no consumers in between) =======
        // x for group g+1 (harmless wrap on last iter; L1 hit)
        {
            const __half* xg1 = g_xh + ((g + 1) & (NG - 1)) * GS + klo;
            #pragma unroll
            for (int b = 0; b < BATCH; ++b)
                xb[cur ^ 1][b] = ldg_xh(xg1 + b * IN_F);
        }
        // weights for group g+WDEPTH into the slot just consumed (guarded: no
        // wasted wrapped DRAM reads on the last WDEPTH iterations)
        if (g + WDEPTH < NG) {
            const int gn = g + WDEPTH;
            #pragma unroll
            for (int o = 0; o < OPW; ++o)
                qbuf[wcur][o] = ldg_cs(qbase + gn * GS + o * IN_F);
        }
        // scales for group g+1
        sv0 = ldg_cs4(sc + ((g + 1) & (NG - 1)) * OUT_F + n0);
        // =====================================================================

        // convert current weight group: qs[o] = (s*q0,s*q1),(s*q2,s*q3)
        u64 qs[OPW][2];
        {
            const float sa[OPW] = {sv.x, sv.y, sv.z, sv.w};
            #pragma unroll
            for (int o = 0; o < OPW; ++o) {
                u64 s2 = pack2(sa[o], sa[o]);
                qs[o][0] = mul2(pack2((float)q[o].x, (float)q[o].y), s2);
                qs[o][1] = mul2(pack2((float)q[o].z, (float)q[o].w), s2);
            }
        }

        // math for group g from xb[cur] (loaded at top of iteration g-1)
        #pragma unroll
        for (int b = 0; b < BATCH; ++b) {
            const uint2 xv = xb[cur][b];
            float2 f01 = __half22float2(*(const __half2*)&xv.x);
            float2 f23 = __half22float2(*(const __half2*)&xv.y);
            u64 x01 = pack2(f01.x, f01.y);
            u64 x23 = pack2(f23.x, f23.y);
            #pragma unroll
            for (int o = 0; o < OPW; ++o) {
                acc[o][b] = fma2(x01, qs[o][0], acc[o][b]);
                acc[o][b] = fma2(x23, qs[o][1], acc[o][b]);
            }
        }
    }

    // ---- pair-halves add, butterfly across 32 lanes ----
    float r[OPW][BATCH];
    #pragma unroll
    for (int o = 0; o < OPW; ++o)
        #pragma unroll
        for (int b = 0; b < BATCH; ++b) {
            float lo, hi; unpack2(acc[o][b], lo, hi);
            r[o][b] = lo + hi;
        }
    #pragma unroll
    for (int off = 16; off > 0; off >>= 1)
        #pragma unroll
        for (int o = 0; o < OPW; ++o)
            #pragma unroll
            for (int b = 0; b < BATCH; ++b)
                r[o][b] += __shfl_xor_sync(0xffffffffu, r[o][b], off);

    if (lane == 0) {
        #pragma unroll
        for (int o = 0; o < OPW; ++o)
            #pragma unroll
            for (int b = 0; b < BATCH; ++b)
                bounce[o * BATCH + b] = r[o][b];
    }
    __syncwarp();

    // 32 results, one per lane; fold in zero/offset term
    const int o = lane >> 3, b = lane & 7;
    const int n = n0 + o;
    float offt = 0.f;
    #pragma unroll
    for (int g2 = 0; g2 < NG; ++g2) {
        float s = __ldg(sc + g2 * OUT_F + n);
        float z = __ldg(zr + g2 * OUT_F + n);
        offt = fmaf(z - 8.f * s, g_sx[b * NG + g2], offt);
    }
    out[b * OUT_F + n] = bounce[lane] + offt;
}

extern "C" void kernel_launch(void* const* d_in, const int* in_sizes, int n_in,
                              void* d_out, int out_size) {
    const float* x  = (const float*)d_in[0];
    const int*   qw = (const int*)d_in[1];
    const float* sc = (const float*)d_in[2];
    const float* zr = (const float*)d_in[3];
    float* out = (float*)d_out;

    prep_kernel<<<32, 256>>>(x);
    w4a32_main<<<OUT_F / OPW, TPB>>>(qw, sc, zr, out);   // 3072 x 32
}